// round 6
// baseline (speedup 1.0000x reference)
#include <cuda_runtime.h>
#include <cuda_bf16.h>

// model_6408091205990: 1.23M independent tiny GRUs (T=10, I=1, H=5) + FC(5->3).
// Round-6: the kernel sits on a MUFU(tanh) throughput floor (invariant to
// ILP/occupancy changes in rounds 3-5).  r/z sigmoids now evaluated two-per-
// MUFU-slot via tanh.approx.f16x2 (gate errors are damped ~250x by the
// contractive h-blend; n-gate tanh stays f32).  MUFU/step: 15 -> 10.

#define NB 4096
#define NT 10
#define NS 301
#define NH 5
#define NO 3
#define NSEQ (NB * NS)
#define NSEQ_HALF (NSEQ / 2)
#define THREADS 128

typedef unsigned long long ull;

__device__ __forceinline__ ull pack2(float lo, float hi) {
    ull r; asm("mov.b64 %0, {%1, %2};" : "=l"(r) : "f"(lo), "f"(hi)); return r;
}
__device__ __forceinline__ void unpack2(ull v, float& lo, float& hi) {
    asm("mov.b64 {%0, %1}, %2;" : "=f"(lo), "=f"(hi) : "l"(v));
}
__device__ __forceinline__ ull fma2(ull a, ull b, ull c) {
    ull d; asm("fma.rn.f32x2 %0, %1, %2, %3;" : "=l"(d) : "l"(a), "l"(b), "l"(c));
    return d;
}
__device__ __forceinline__ float tanh_mufu(float x) {
    float y; asm("tanh.approx.f32 %0, %1;" : "=f"(y) : "f"(x)); return y;
}
// ---- f16x2 helpers (r/z gate path) -----------------------------------------
__device__ __forceinline__ unsigned h2_from_f32(float lo, float hi) {
    unsigned r; asm("cvt.rn.f16x2.f32 %0, %1, %2;" : "=r"(r) : "f"(hi), "f"(lo));
    return r;   // {lo, hi}
}
__device__ __forceinline__ unsigned tanh_h2(unsigned x) {
    unsigned y; asm("tanh.approx.f16x2 %0, %1;" : "=r"(y) : "r"(x)); return y;
}
__device__ __forceinline__ unsigned hfma2_u(unsigned a, unsigned b, unsigned c) {
    unsigned d; asm("fma.rn.f16x2 %0, %1, %2, %3;" : "=r"(d) : "r"(a), "r"(b), "r"(c));
    return d;
}
__device__ __forceinline__ float h2_lo_f32(unsigned v) {
    float f;
    asm("{ .reg .f16 lo, hi; mov.b32 {lo, hi}, %1; cvt.f32.f16 %0, lo; }"
        : "=f"(f) : "r"(v));
    return f;
}
__device__ __forceinline__ float h2_hi_f32(unsigned v) {
    float f;
    asm("{ .reg .f16 lo, hi; mov.b32 {lo, hi}, %1; cvt.f32.f16 %0, hi; }"
        : "=f"(f) : "r"(v));
    return f;
}

struct GruW {
    ull wrz_x[NH];        // (0.5*w_ih[r][j], 0.5*w_ih[z][j])
    ull brz2[NH];         // 0.5*(b_ih+b_hh) for (r, z)
    ull wrz_h[NH][NH];    // [j][k] = (0.5*w_hh[r,j,k], 0.5*w_hh[z,j,k])
    ull wn_h2[2][NH];     // [p][k] = (w_hh[n,2p,k], w_hh[n,2p+1,k])
    float wn_h4[NH];
    ull bn2[2];
    float bn4;
    ull win2[2], bin2[2];
    float win4, bin4;
    ull NEG1_2;
};

#define H05X2 0x38003800u   // half2(0.5f, 0.5f)

// One GRU step for one sequence (h: 5 scalars, updated in place).
template <bool FIRST>
__device__ __forceinline__ void gru_step(const GruW& W, float h[NH], float xv)
{
    const ull xv2 = pack2(xv, xv);

    ull arz[NH];
    #pragma unroll
    for (int j = 0; j < NH; j++) arz[j] = fma2(xv2, W.wrz_x[j], W.brz2[j]);

    ull an2[2] = {W.bn2[0], W.bn2[1]};
    float ah4 = W.bn4;

    if (!FIRST) {
        ull hb[NH];
        #pragma unroll
        for (int k = 0; k < NH; k++) hb[k] = pack2(h[k], h[k]);
        #pragma unroll
        for (int k = 0; k < NH; k++) {
            #pragma unroll
            for (int j = 0; j < NH; j++)
                arz[j] = fma2(W.wrz_h[j][k], hb[k], arz[j]);
            an2[0] = fma2(W.wn_h2[0][k], hb[k], an2[0]);
            an2[1] = fma2(W.wn_h2[1][k], hb[k], an2[1]);
            ah4 = fmaf(W.wn_h4[k], h[k], ah4);
        }
    }
    float ah[NH];
    unpack2(an2[0], ah[0], ah[1]);
    unpack2(an2[1], ah[2], ah[3]);
    ah[4] = ah4;

    float ai[NH];
    {
        ull ai01 = fma2(xv2, W.win2[0], W.bin2[0]);
        ull ai23 = fma2(xv2, W.win2[1], W.bin2[1]);
        unpack2(ai01, ai[0], ai[1]);
        unpack2(ai23, ai[2], ai[3]);
        ai[4] = fmaf(xv, W.win4, W.bin4);
    }

    // r/z gates: one tanh.f16x2 per j (2 sigmoids per MUFU slot);
    // n gate: f32 tanh (feeds h directly, keep precision).
    float z[NH], nn[NH];
    #pragma unroll
    for (int j = 0; j < NH; j++) {
        float ar, az;
        unpack2(arz[j], ar, az);                    // 0.5-scaled preacts
        unsigned t2 = tanh_h2(h2_from_f32(ar, az));
        unsigned rz = hfma2_u(t2, H05X2, H05X2);    // sigmoid = 0.5*t + 0.5
        const float r = h2_lo_f32(rz);
        z[j] = h2_hi_f32(rz);
        nn[j] = tanh_mufu(fmaf(r, ah[j], ai[j]));
    }

    // h update (1-z)*n + z*h = z*(h-n) + n, j-pair packed
    {
        ull h01 = pack2(h[0], h[1]);
        ull h23 = pack2(h[2], h[3]);
        ull nn01 = pack2(nn[0], nn[1]);
        ull nn23 = pack2(nn[2], nn[3]);
        ull z01  = pack2(z[0], z[1]);
        ull z23  = pack2(z[2], z[3]);
        h01 = fma2(z01, fma2(nn01, W.NEG1_2, h01), nn01);
        h23 = fma2(z23, fma2(nn23, W.NEG1_2, h23), nn23);
        h[4] = fmaf(z[4], h[4] - nn[4], nn[4]);
        unpack2(h01, h[0], h[1]);
        unpack2(h23, h[2], h[3]);
    }
}

__global__ __launch_bounds__(THREADS, 4)
void gru_fused_kernel(const float* __restrict__ x,
                      const float* __restrict__ w_ih,
                      const float* __restrict__ w_hh,
                      const float* __restrict__ b_ih,
                      const float* __restrict__ b_hh,
                      const float* __restrict__ fc_w,
                      const float* __restrict__ fc_b,
                      float* __restrict__ out)
{
    const int i = blockIdx.x * THREADS + threadIdx.x;
    if (i >= NSEQ_HALF) return;
    // Two coalesced sequences per thread.
    const int nA = i;
    const int nB = i + NSEQ_HALF;
    const int bA = nA / NS, sA = nA - bA * NS;
    const int bB = nB / NS, sB = nB - bB * NS;

    // ---- weight prep (uniform broadcast loads; shared by both sequences) ----
    GruW W;
    #pragma unroll
    for (int j = 0; j < NH; j++) {
        W.wrz_x[j] = pack2(0.5f * __ldg(&w_ih[j]), 0.5f * __ldg(&w_ih[NH + j]));
        W.brz2[j]  = pack2(0.5f * (__ldg(&b_ih[j]) + __ldg(&b_hh[j])),
                           0.5f * (__ldg(&b_ih[NH + j]) + __ldg(&b_hh[NH + j])));
        #pragma unroll
        for (int k = 0; k < NH; k++)
            W.wrz_h[j][k] = pack2(0.5f * __ldg(&w_hh[j * NH + k]),
                                  0.5f * __ldg(&w_hh[(NH + j) * NH + k]));
    }
    #pragma unroll
    for (int p = 0; p < 2; p++) {
        W.bn2[p]  = pack2(__ldg(&b_hh[2 * NH + 2 * p]), __ldg(&b_hh[2 * NH + 2 * p + 1]));
        W.win2[p] = pack2(__ldg(&w_ih[2 * NH + 2 * p]), __ldg(&w_ih[2 * NH + 2 * p + 1]));
        W.bin2[p] = pack2(__ldg(&b_ih[2 * NH + 2 * p]), __ldg(&b_ih[2 * NH + 2 * p + 1]));
        #pragma unroll
        for (int k = 0; k < NH; k++)
            W.wn_h2[p][k] = pack2(__ldg(&w_hh[(2 * NH + 2 * p) * NH + k]),
                                  __ldg(&w_hh[(2 * NH + 2 * p + 1) * NH + k]));
    }
    W.bn4  = __ldg(&b_hh[2 * NH + 4]);
    W.win4 = __ldg(&w_ih[2 * NH + 4]);
    W.bin4 = __ldg(&b_ih[2 * NH + 4]);
    #pragma unroll
    for (int k = 0; k < NH; k++) W.wn_h4[k] = __ldg(&w_hh[(2 * NH + 4) * NH + k]);
    W.NEG1_2 = pack2(-1.0f, -1.0f);

    // ---- two interleaved recurrences ---------------------------------------
    float hA[NH] = {0.f, 0.f, 0.f, 0.f, 0.f};
    float hB[NH] = {0.f, 0.f, 0.f, 0.f, 0.f};
    const float* xpA = x + (size_t)bA * (NT * NS) + sA;
    const float* xpB = x + (size_t)bB * (NT * NS) + sB;

    {
        const float xvA = __ldg(xpA);
        const float xvB = __ldg(xpB);
        gru_step<true>(W, hA, xvA);
        gru_step<true>(W, hB, xvB);
    }
    #pragma unroll
    for (int t = 1; t < NT; t++) {
        const float xvA = __ldg(xpA + t * NS);
        const float xvB = __ldg(xpB + t * NS);
        gru_step<false>(W, hA, xvA);
        gru_step<false>(W, hB, xvB);
    }

    // ---- FC(5 -> 3), strided writes out[b][o][s] ----------------------------
    #pragma unroll
    for (int o = 0; o < NO; o++) {
        float wc[NH];
        #pragma unroll
        for (int k = 0; k < NH; k++) wc[k] = __ldg(&fc_w[o * NH + k]);
        const float bc = __ldg(&fc_b[o]);
        float yA = bc, yB = bc;
        #pragma unroll
        for (int k = 0; k < NH; k++) {
            yA = fmaf(wc[k], hA[k], yA);
            yB = fmaf(wc[k], hB[k], yB);
        }
        out[((size_t)bA * NO + o) * NS + sA] = yA;
        out[((size_t)bB * NO + o) * NS + sB] = yB;
    }
}

extern "C" void kernel_launch(void* const* d_in, const int* in_sizes, int n_in,
                              void* d_out, int out_size)
{
    const float* x    = (const float*)d_in[0];
    const float* w_ih = (const float*)d_in[1];
    const float* w_hh = (const float*)d_in[2];
    const float* b_ih = (const float*)d_in[3];
    const float* b_hh = (const float*)d_in[4];
    const float* fc_w = (const float*)d_in[5];
    const float* fc_b = (const float*)d_in[6];
    float* out = (float*)d_out;

    const int grid = (NSEQ_HALF + THREADS - 1) / THREADS;
    gru_fused_kernel<<<grid, THREADS>>>(x, w_ih, w_hh, b_ih, b_hh, fc_w, fc_b, out);
}